// round 2
// baseline (speedup 1.0000x reference)
#include <cuda_runtime.h>

#define G_TOTAL 32768
#define H1      150
#define PP      8

using u64 = unsigned long long;

// ---- packed f32x2 helpers (Blackwell sm_103a) ------------------------------
__device__ __forceinline__ u64 pk2(float a, float b) {
    u64 r;
    asm("mov.b64 %0,{%1,%2};" : "=l"(r)
        : "r"(__float_as_uint(a)), "r"(__float_as_uint(b)));
    return r;
}
__device__ __forceinline__ float2 upk2(u64 v) {
    unsigned lo, hi;
    asm("mov.b64 {%0,%1},%2;" : "=r"(lo), "=r"(hi) : "l"(v));
    return make_float2(__uint_as_float(lo), __uint_as_float(hi));
}
__device__ __forceinline__ u64 fma2(u64 a, u64 b, u64 c) {
    u64 d;
    asm("fma.rn.f32x2 %0,%1,%2,%3;" : "=l"(d) : "l"(a), "l"(b), "l"(c));
    return d;
}

// ---- shared-memory layout (floats) -----------------------------------------
// W1d : [150][36]  duplicated-transposed W1 rows ({w,w} pairs, k-major in row)
// W2d : [150][16]  duplicated W2 rows
// W3t : [150][40]  transposed W3 rows
#define SM_W1D 0
#define SM_W2D 5400
#define SM_W3T 7800
#define SM_B1  13800
#define SM_B3  13950
#define SM_W4  14100
#define SM_B2  14250
#define SM_FLOATS 14260
#define SM_BYTES  (SM_FLOATS * 4)

// ---- per-group tail: warp stats over 32 lanes + group MLP ------------------
__device__ __noinline__ float group_tail(float a0, float a1, float a2, float a3,
                                         float a4, float a5, float a6, float a7,
                                         const float* __restrict__ W3t,
                                         const float* __restrict__ b3s,
                                         const float* __restrict__ W4s,
                                         float b4v, int lane)
{
    float a[PP] = {a0, a1, a2, a3, a4, a5, a6, a7};
    u64 ag[20];   // packed agg pairs: ag[stat*4 + p/2] = {agg_p, agg_p+1}

    #pragma unroll
    for (int ph = 0; ph < 4; ++ph) {
        float va = a[2 * ph], vb = a[2 * ph + 1];

        // mean (both features interleaved for ILP)
        float sa = va, sb = vb;
        #pragma unroll
        for (int o = 16; o; o >>= 1) {
            sa += __shfl_xor_sync(0xffffffffu, sa, o);
            sb += __shfl_xor_sync(0xffffffffu, sb, o);
        }
        float meana = sa * (1.0f / 32.0f), meanb = sb * (1.0f / 32.0f);

        // unbiased variance (two-pass)
        float da = va - meana, db = vb - meanb;
        float qa = da * da, qb = db * db;
        #pragma unroll
        for (int o = 16; o; o >>= 1) {
            qa += __shfl_xor_sync(0xffffffffu, qa, o);
            qb += __shfl_xor_sync(0xffffffffu, qb, o);
        }
        float vara = qa * (1.0f / 31.0f), varb = qb * (1.0f / 31.0f);

        // min / max
        float mna = va, mxa = va, mnb = vb, mxb = vb;
        #pragma unroll
        for (int o = 16; o; o >>= 1) {
            mna = fminf(mna, __shfl_xor_sync(0xffffffffu, mna, o));
            mxa = fmaxf(mxa, __shfl_xor_sync(0xffffffffu, mxa, o));
            mnb = fminf(mnb, __shfl_xor_sync(0xffffffffu, mnb, o));
            mxb = fmaxf(mxb, __shfl_xor_sync(0xffffffffu, mxb, o));
        }

        // lower median via warp bitonic sort (two sorts interleaved)
        float ta = va, tb = vb;
        #pragma unroll
        for (int k = 2; k <= 32; k <<= 1) {
            #pragma unroll
            for (int j = k >> 1; j > 0; j >>= 1) {
                float oa = __shfl_xor_sync(0xffffffffu, ta, j);
                float ob = __shfl_xor_sync(0xffffffffu, tb, j);
                bool keep_lo = (((lane & j) == 0) == ((lane & k) == 0));
                float la = fminf(ta, oa), ha = fmaxf(ta, oa);
                float lb = fminf(tb, ob), hb = fmaxf(tb, ob);
                ta = keep_lo ? la : ha;
                tb = keep_lo ? lb : hb;
            }
        }
        float meda = __shfl_sync(0xffffffffu, ta, 15);
        float medb = __shfl_sync(0xffffffffu, tb, 15);

        ag[0 * 4 + ph] = pk2(meana, meanb);
        ag[1 * 4 + ph] = pk2(vara, varb);
        ag[2 * 4 + ph] = pk2(mna, mnb);
        ag[3 * 4 + ph] = pk2(meda, medb);
        ag[4 * 4 + ph] = pk2(mxa, mxb);
    }

    // group MLP: 40 -> 150 (relu) -> 1, hidden units strided over lanes,
    // packed f32x2 dot products with two accumulator chains
    float zp = 0.0f;
    #pragma unroll 1
    for (int j = lane; j < H1; j += 32) {
        const ulonglong2* wr = (const ulonglong2*)(W3t + j * 40);
        u64 t2a = 0ull, t2b = 0ull;
        #pragma unroll
        for (int q = 0; q < 10; ++q) {
            ulonglong2 w = wr[q];
            t2a = fma2(ag[2 * q],     w.x, t2a);
            t2b = fma2(ag[2 * q + 1], w.y, t2b);
        }
        float2 sa = upk2(t2a), sb = upk2(t2b);
        float t = (sa.x + sa.y) + (sb.x + sb.y) + b3s[j];
        t = fmaxf(t, 0.0f);
        zp = fmaf(t, W4s[j], zp);
    }
    #pragma unroll
    for (int o = 16; o; o >>= 1) zp += __shfl_xor_sync(0xffffffffu, zp, o);

    return 1.0f / (1.0f + __expf(-(zp + b4v)));
}

__global__ void __launch_bounds__(256, 1)
minn_fused_f32x2_kernel(const float* __restrict__ x,
                        const int*   __restrict__ kmer,
                        const int*   __restrict__ indices,
                        const float* __restrict__ emb,
                        const float* __restrict__ W1, const float* __restrict__ b1,
                        const float* __restrict__ W2, const float* __restrict__ b2,
                        const float* __restrict__ W3, const float* __restrict__ b3,
                        const float* __restrict__ W4, const float* __restrict__ b4,
                        float* __restrict__ out)
{
    extern __shared__ float sm[];
    float* W1d = sm + SM_W1D;
    float* W2d = sm + SM_W2D;
    float* W3t = sm + SM_W3T;
    float* b1s = sm + SM_B1;
    float* b3s = sm + SM_B3;
    float* W4s = sm + SM_W4;
    float* b2s = sm + SM_B2;

    const int tid = threadIdx.x;

    // ---- stage weights: duplicate + transpose for vector broadcast loads ----
    for (int i = tid; i < H1 * 18; i += 256) {
        int j = i / 18, k = i - j * 18;
        float w = W1[k * H1 + j];
        W1d[j * 36 + 2 * k]     = w;
        W1d[j * 36 + 2 * k + 1] = w;
    }
    for (int i = tid; i < H1 * PP; i += 256) {
        int j = i >> 3, p = i & 7;
        float w = W2[i];
        W2d[j * 16 + 2 * p]     = w;
        W2d[j * 16 + 2 * p + 1] = w;
    }
    for (int i = tid; i < 40 * H1; i += 256) {
        int j = i / 40, k = i - j * 40;
        W3t[i] = W3[k * H1 + j];
    }
    for (int i = tid; i < H1; i += 256) {
        b1s[i] = b1[i];
        b3s[i] = b3[i];
        W4s[i] = W4[i];
    }
    if (tid < PP) b2s[tid] = b2[tid];
    const float b4v = __ldg(b4);
    __syncthreads();

    const int warp = tid >> 5;
    const int lane = tid & 31;
    const int g0 = (blockIdx.x * 8 + warp) * 4;   // 4 groups per warp

    // ---- gather the 4 reads this lane owns, packed as two f32x2 streams ----
    const int r0 = indices[(g0 + 0) * 32 + lane];
    const int r1 = indices[(g0 + 1) * 32 + lane];
    const int r2 = indices[(g0 + 2) * 32 + lane];
    const int r3 = indices[(g0 + 3) * 32 + lane];

    u64 inA[18], inB[18];   // A = {read g0, read g1}, B = {read g2, read g3}
    {
        const float4* p0 = (const float4*)(x + (size_t)r0 * 16);
        const float4* p1 = (const float4*)(x + (size_t)r1 * 16);
        const float4* p2 = (const float4*)(x + (size_t)r2 * 16);
        const float4* p3 = (const float4*)(x + (size_t)r3 * 16);
        #pragma unroll
        for (int q = 0; q < 4; ++q) {
            float4 v0 = p0[q], v1 = p1[q], v2 = p2[q], v3 = p3[q];
            inA[4 * q + 0] = pk2(v0.x, v1.x);  inB[4 * q + 0] = pk2(v2.x, v3.x);
            inA[4 * q + 1] = pk2(v0.y, v1.y);  inB[4 * q + 1] = pk2(v2.y, v3.y);
            inA[4 * q + 2] = pk2(v0.z, v1.z);  inB[4 * q + 2] = pk2(v2.z, v3.z);
            inA[4 * q + 3] = pk2(v0.w, v1.w);  inB[4 * q + 3] = pk2(v2.w, v3.w);
        }
        float2 e0 = ((const float2*)emb)[kmer[r0]];
        float2 e1 = ((const float2*)emb)[kmer[r1]];
        float2 e2 = ((const float2*)emb)[kmer[r2]];
        float2 e3 = ((const float2*)emb)[kmer[r3]];
        inA[16] = pk2(e0.x, e1.x);  inA[17] = pk2(e0.y, e1.y);
        inB[16] = pk2(e2.x, e3.x);  inB[17] = pk2(e2.y, e3.y);
    }

    // ---- per-read MLP 18->150(relu)->8(relu), packed f32x2, 4 reads/lane ----
    u64 aA[PP], aB[PP];
    #pragma unroll
    for (int p = 0; p < PP; ++p) {
        float bp = b2s[p];
        u64 z = pk2(bp, bp);
        aA[p] = z; aB[p] = z;
    }

    #pragma unroll 2
    for (int j = 0; j < H1; ++j) {
        float bj = b1s[j];
        u64 hA = pk2(bj, bj), hB = hA;
        const ulonglong2* w1r = (const ulonglong2*)(W1d + j * 36);
        #pragma unroll
        for (int q = 0; q < 9; ++q) {
            ulonglong2 w = w1r[q];
            hA = fma2(inA[2 * q],     w.x, hA);
            hB = fma2(inB[2 * q],     w.x, hB);
            hA = fma2(inA[2 * q + 1], w.y, hA);
            hB = fma2(inB[2 * q + 1], w.y, hB);
        }
        float2 ra = upk2(hA), rb = upk2(hB);
        hA = pk2(fmaxf(ra.x, 0.0f), fmaxf(ra.y, 0.0f));
        hB = pk2(fmaxf(rb.x, 0.0f), fmaxf(rb.y, 0.0f));

        const ulonglong2* w2r = (const ulonglong2*)(W2d + j * 16);
        #pragma unroll
        for (int q = 0; q < 4; ++q) {
            ulonglong2 w = w2r[q];
            aA[2 * q]     = fma2(hA, w.x, aA[2 * q]);
            aB[2 * q]     = fma2(hB, w.x, aB[2 * q]);
            aA[2 * q + 1] = fma2(hA, w.y, aA[2 * q + 1]);
            aB[2 * q + 1] = fma2(hB, w.y, aB[2 * q + 1]);
        }
    }

    // unpack per-group activations (+final relu)
    float s0[PP], s1[PP], s2[PP], s3[PP];
    #pragma unroll
    for (int p = 0; p < PP; ++p) {
        float2 t = upk2(aA[p]);
        s0[p] = fmaxf(t.x, 0.0f);
        s1[p] = fmaxf(t.y, 0.0f);
        float2 u = upk2(aB[p]);
        s2[p] = fmaxf(u.x, 0.0f);
        s3[p] = fmaxf(u.y, 0.0f);
    }

    // ---- per-group aggregation + group MLP ----
    float o0 = group_tail(s0[0], s0[1], s0[2], s0[3], s0[4], s0[5], s0[6], s0[7],
                          W3t, b3s, W4s, b4v, lane);
    if (lane == 0) out[g0 + 0] = o0;
    float o1 = group_tail(s1[0], s1[1], s1[2], s1[3], s1[4], s1[5], s1[6], s1[7],
                          W3t, b3s, W4s, b4v, lane);
    if (lane == 0) out[g0 + 1] = o1;
    float o2 = group_tail(s2[0], s2[1], s2[2], s2[3], s2[4], s2[5], s2[6], s2[7],
                          W3t, b3s, W4s, b4v, lane);
    if (lane == 0) out[g0 + 2] = o2;
    float o3 = group_tail(s3[0], s3[1], s3[2], s3[3], s3[4], s3[5], s3[6], s3[7],
                          W3t, b3s, W4s, b4v, lane);
    if (lane == 0) out[g0 + 3] = o3;
}

extern "C" void kernel_launch(void* const* d_in, const int* in_sizes, int n_in,
                              void* d_out, int out_size)
{
    const float* x       = (const float*)d_in[0];
    const int*   kmer    = (const int*)  d_in[1];
    const int*   indices = (const int*)  d_in[2];
    const float* emb     = (const float*)d_in[3];
    const float* W1      = (const float*)d_in[4];
    const float* b1      = (const float*)d_in[5];
    const float* W2      = (const float*)d_in[6];
    const float* b2      = (const float*)d_in[7];
    const float* W3      = (const float*)d_in[8];
    const float* b3      = (const float*)d_in[9];
    const float* W4      = (const float*)d_in[10];
    const float* b4      = (const float*)d_in[11];
    float* out = (float*)d_out;

    cudaFuncSetAttribute(minn_fused_f32x2_kernel,
                         cudaFuncAttributeMaxDynamicSharedMemorySize, SM_BYTES);

    // 8 warps/block * 4 groups/warp = 32 groups per block
    const int blocks = G_TOTAL / 32;   // 1024
    minn_fused_f32x2_kernel<<<blocks, 256, SM_BYTES>>>(
        x, kmer, indices, emb, W1, b1, W2, b2, W3, b3, W4, b4, out);
}